// round 8
// baseline (speedup 1.0000x reference)
#include <cuda_runtime.h>
#include <cuda_bf16.h>

#define IMAGE_SIZE 32
#define T_MAX 50
#define D2_LUT 206   // masks are exactly 1.0f for d2 >= 205 (exp < 2^-25 rounds away)

// ---------- compile-time LUT ----------
constexpr double cexp(double x) {
    const double LN2 = 0.6931471805599453;
    const double INV_LN2 = 1.4426950408889634;
    double tt = x * INV_LN2;
    int n = (int)(tt >= 0.0 ? tt + 0.5 : tt - 0.5);
    double r = x - (double)n * LN2;          // |r| <= 0.3466
    double s = 1.0, term = 1.0;
    for (int k = 1; k <= 13; k++) { term *= r / (double)k; s += term; }
    double p = 1.0;
    int m = n;
    while (m <= -16) { p *= 0.0000152587890625; m += 16; }  // 2^-16
    while (m < 0)    { p *= 0.5;  m++; }
    while (m > 0)    { p *= 2.0;  m--; }
    return s * p;
}

struct Lut {
    float v[T_MAX * D2_LUT];
    constexpr Lut() : v{} {
        for (int d2 = 0; d2 < D2_LUT; d2++) {
            double m = 1.0;
            for (int i = 1; i <= T_MAX; i++) {
                double beta = 1.0 + 0.1 * (double)(i - 1);
                double g = cexp(-(double)d2 / (2.0 * beta));
                m *= (1.0 - g);
                v[(i - 1) * D2_LUT + d2] = (d2 >= 205) ? 1.0f : (float)m;
            }
        }
    }
};

__device__ constexpr Lut g_lut{};

#define GRID_PERSISTENT 1184   // 148 SMs * 8 CTAs

// ---------- single persistent streaming kernel ----------
// 1184 CTAs x 256 threads, each CTA loops over images with stride gridDim.x.
// Thread = (y, 4-wide x group), identical coalesced float4 pattern to the
// best one-shot version; the loop lets the compiler pipeline next-iteration
// loads under current-iteration stores.
__global__ __launch_bounds__(256, 8)
void apply_mask_kernel(const float* __restrict__ x0,
                       const int*   __restrict__ t,
                       const float* __restrict__ cx,
                       const float* __restrict__ cy,
                       float* __restrict__ out,
                       int B) {
    int tid   = threadIdx.x;
    int y     = tid >> 3;        // 0..31
    int xbase = (tid & 7) << 2;  // 0,4,...,28

    float fy  = (float)y;
    float fx0 = (float)(xbase + 0), fx1 = (float)(xbase + 1);
    float fx2 = (float)(xbase + 2), fx3 = (float)(xbase + 3);

    size_t tile_off = (size_t)y * IMAGE_SIZE + xbase;

    for (int b = blockIdx.x; b < B; b += GRID_PERSISTENT) {
        size_t pix = (size_t)b * 3072 + tile_off;

        // Streaming loads first — independent of the LUT path.
        float4 v0 = __ldg(reinterpret_cast<const float4*>(x0 + pix));
        float4 v1 = __ldg(reinterpret_cast<const float4*>(x0 + pix + 1024));
        float4 v2 = __ldg(reinterpret_cast<const float4*>(x0 + pix + 2048));

        float fcx = __ldg(&cx[b]);
        float fcy = __ldg(&cy[b]);
        int   tt  = __ldg(&t[b]);  // in [1, 50]

        float dy  = fy - fcy;
        float dy2 = dy * dy;
        float e0 = fx0 - fcx, e1 = fx1 - fcx, e2 = fx2 - fcx, e3 = fx3 - fcx;

        const float* __restrict__ lrow = g_lut.v + (tt - 1) * D2_LUT;
        float m0 = __ldg(&lrow[min((int)(e0 * e0 + dy2), 205)]);
        float m1 = __ldg(&lrow[min((int)(e1 * e1 + dy2), 205)]);
        float m2 = __ldg(&lrow[min((int)(e2 * e2 + dy2), 205)]);
        float m3 = __ldg(&lrow[min((int)(e3 * e3 + dy2), 205)]);

        v0.x *= m0; v0.y *= m1; v0.z *= m2; v0.w *= m3;
        v1.x *= m0; v1.y *= m1; v1.z *= m2; v1.w *= m3;
        v2.x *= m0; v2.y *= m1; v2.z *= m2; v2.w *= m3;

        *reinterpret_cast<float4*>(out + pix)        = v0;
        *reinterpret_cast<float4*>(out + pix + 1024) = v1;
        *reinterpret_cast<float4*>(out + pix + 2048) = v2;
    }
}

extern "C" void kernel_launch(void* const* d_in, const int* in_sizes, int n_in,
                              void* d_out, int out_size) {
    const float* x0 = (const float*)d_in[0];
    const int*   t  = (const int*)d_in[1];
    const float* cx = (const float*)d_in[2];
    const float* cy = (const float*)d_in[3];
    float* out = (float*)d_out;

    int B = in_sizes[1];  // t has B elements

    apply_mask_kernel<<<GRID_PERSISTENT, 256>>>(x0, t, cx, cy, out, B);
}

// round 9
// speedup vs baseline: 1.1483x; 1.1483x over previous
#include <cuda_runtime.h>
#include <cuda_bf16.h>

#define IMAGE_SIZE 32
#define T_MAX 50
#define D2_LUT 206   // masks are exactly 1.0f for d2 >= 205 (exp < 2^-25 rounds away)

// ---------- compile-time LUT ----------
constexpr double cexp(double x) {
    const double LN2 = 0.6931471805599453;
    const double INV_LN2 = 1.4426950408889634;
    double tt = x * INV_LN2;
    int n = (int)(tt >= 0.0 ? tt + 0.5 : tt - 0.5);
    double r = x - (double)n * LN2;          // |r| <= 0.3466
    double s = 1.0, term = 1.0;
    for (int k = 1; k <= 13; k++) { term *= r / (double)k; s += term; }
    double p = 1.0;
    int m = n;
    while (m <= -16) { p *= 0.0000152587890625; m += 16; }  // 2^-16
    while (m < 0)    { p *= 0.5;  m++; }
    while (m > 0)    { p *= 2.0;  m--; }
    return s * p;
}

struct Lut {
    // v[(t-1)*D2_LUT + d2] = prod_{i=1..t} (1 - exp(-d2/(2*beta_i))); col 205 == 1.0f
    float v[T_MAX * D2_LUT];
    constexpr Lut() : v{} {
        for (int d2 = 0; d2 < D2_LUT; d2++) {
            double m = 1.0;
            for (int i = 1; i <= T_MAX; i++) {
                double beta = 1.0 + 0.1 * (double)(i - 1);
                double g = cexp(-(double)d2 / (2.0 * beta));
                m *= (1.0 - g);
                v[(i - 1) * D2_LUT + d2] = (d2 >= 205) ? 1.0f : (float)m;
            }
        }
    }
};

__device__ constexpr Lut g_lut{};

// ---------- single streaming kernel (best measured config: R6) ----------
// One block = 2 consecutive images, 512 threads. Threads 0..255 -> image 2b,
// 256..511 -> image 2b+1; within each image: 32 rows x 8 float4 groups.
// All addressing in 32-bit (B*3072 < 2^31) to shorten IMAD chains.
__global__ __launch_bounds__(512, 4)
void apply_mask_kernel(const float* __restrict__ x0,
                       const int*   __restrict__ t,
                       const float* __restrict__ cx,
                       const float* __restrict__ cy,
                       float* __restrict__ out) {
    unsigned tid  = threadIdx.x;
    unsigned b    = blockIdx.x * 2u + (tid >> 8);  // image index
    unsigned lt   = tid & 255u;
    unsigned y    = lt >> 3;         // 0..31
    unsigned xbase = (lt & 7u) << 2; // 0,4,...,28

    // x0 layout: [B, 3, 32, 32]; channel stride = 1024 floats.
    unsigned pix = b * 3072u + y * IMAGE_SIZE + xbase;

    // Kick off the three streaming loads first — independent of the LUT.
    float4 v0 = __ldg(reinterpret_cast<const float4*>(x0 + pix));
    float4 v1 = __ldg(reinterpret_cast<const float4*>(x0 + pix + 1024u));
    float4 v2 = __ldg(reinterpret_cast<const float4*>(x0 + pix + 2048u));

    // Uniform per half-block: broadcast within each warp.
    float fcx = __ldg(&cx[b]);
    float fcy = __ldg(&cy[b]);
    int   tt  = __ldg(&t[b]);  // in [1, 50]

    float dy  = (float)y - fcy;
    float dy2 = dy * dy;

    const float* __restrict__ lrow = g_lut.v + (tt - 1) * D2_LUT;

    float e0 = (float)(xbase + 0u) - fcx;
    float e1 = (float)(xbase + 1u) - fcx;
    float e2 = (float)(xbase + 2u) - fcx;
    float e3 = (float)(xbase + 3u) - fcx;
    // dx, dy are integer-valued; d2 <= 1922 is exact in fp32.
    int d0 = min((int)(e0 * e0 + dy2), 205);
    int d1 = min((int)(e1 * e1 + dy2), 205);
    int d2 = min((int)(e2 * e2 + dy2), 205);
    int d3 = min((int)(e3 * e3 + dy2), 205);
    float m0 = __ldg(&lrow[d0]);
    float m1 = __ldg(&lrow[d1]);
    float m2 = __ldg(&lrow[d2]);
    float m3 = __ldg(&lrow[d3]);

    v0.x *= m0; v0.y *= m1; v0.z *= m2; v0.w *= m3;
    v1.x *= m0; v1.y *= m1; v1.z *= m2; v1.w *= m3;
    v2.x *= m0; v2.y *= m1; v2.z *= m2; v2.w *= m3;

    *reinterpret_cast<float4*>(out + pix)         = v0;
    *reinterpret_cast<float4*>(out + pix + 1024u) = v1;
    *reinterpret_cast<float4*>(out + pix + 2048u) = v2;
}

extern "C" void kernel_launch(void* const* d_in, const int* in_sizes, int n_in,
                              void* d_out, int out_size) {
    const float* x0 = (const float*)d_in[0];
    const int*   t  = (const int*)d_in[1];
    const float* cx = (const float*)d_in[2];
    const float* cy = (const float*)d_in[3];
    float* out = (float*)d_out;

    int B = in_sizes[1];  // t has B elements

    apply_mask_kernel<<<B / 2, 512>>>(x0, t, cx, cy, out);
}